// round 13
// baseline (speedup 1.0000x reference)
#include <cuda_runtime.h>
#include <cuda_fp16.h>
#include <cstdint>

#define CIN   128
#define HW    96
#define HWSZ  9216
#define BATCH 4
#define OC1   128
#define OC2   108
#define NDG   4

// ---------------- scratch (static device globals; no allocs) ----------------
__device__ float    g_xres[BATCH * OC1 * HWSZ];  // conv1 output
__device__ float    g_co  [BATCH * OC2 * HWSZ];  // conv2 output
__device__ float    g_xp  [BATCH * NDG * HWSZ * 32]; // x channel-last fp32 [b][g][pix][32]
// fp16 weights, group-packed + rotation-swizzled: [chunk][oc][slot(8)][hl(2)] u32=half2
__device__ uint32_t g_wA1h[36 * 128 * 16];
__device__ uint32_t g_wA2h[36 * 128 * 16];
__device__ uint32_t g_wdh [36 * 128 * 16];

// ---------------- helpers ----------------
__device__ __forceinline__ void mma16(float c[4], const uint32_t a[4], const uint32_t b[2]) {
    asm volatile("mma.sync.aligned.m16n8k16.row.col.f32.f16.f16.f32 "
        "{%0,%1,%2,%3}, {%4,%5,%6,%7}, {%8,%9}, {%0,%1,%2,%3};"
        : "+f"(c[0]), "+f"(c[1]), "+f"(c[2]), "+f"(c[3])
        : "r"(a[0]), "r"(a[1]), "r"(a[2]), "r"(a[3]), "r"(b[0]), "r"(b[1]));
}
__device__ __forceinline__ uint32_t pack_h2(float a, float b) {
    __half2 h = __floats2half2_rn(a, b);
    return *reinterpret_cast<uint32_t*>(&h);
}
__device__ __forceinline__ uint32_t smem_u32(const void* p) {
    return (uint32_t)__cvta_generic_to_shared(p);
}
__device__ __forceinline__ void cp_async16(uint32_t saddr, const void* g) {
    asm volatile("cp.async.cg.shared.global [%0], [%1], 16;" :: "r"(saddr), "l"(g));
}
#define CP_WAIT_ALL() asm volatile("cp.async.wait_all;" ::: "memory")

// async copy of one 8KB weight chunk (2048 u32, flat)
__device__ __forceinline__ void prefetch_w_cp(uint32_t* dst, const uint32_t* src, int tid) {
    uint32_t base = smem_u32(dst);
#pragma unroll
    for (int j = 0; j < 2; j++) {
        int t4 = tid + j * 256;
        cp_async16(base + t4 * 16, src + t4 * 4);
    }
}

// ---------------- weight prep (shared by conv1/conv2/dcn) ----------------
__global__ void prep_wh_kernel(const float* __restrict__ w, int OC, int which) {
    uint32_t* dst = (which == 0) ? g_wA1h : (which == 1) ? g_wA2h : g_wdh;
    int i = blockIdx.x * 256 + threadIdx.x;
    if (i >= 36 * 128 * 16) return;
    int j = i & 15, oc = (i >> 4) & 127, chunk = i >> 11;
    int slot = j >> 1, hl = j & 1;
    int g2 = (slot - oc) & 7;
    int s = g2 >> 2, lkp = g2 & 3;
    int kb = 16 * s + 2 * lkp + 8 * hl;
    int grp = chunk / 9, ktap = chunk % 9;
    int ic0 = grp * 32 + kb;
    float v0 = 0.f, v1 = 0.f;
    if (oc < OC) {
        v0 = w[(oc * CIN + ic0) * 9 + ktap];
        v1 = w[(oc * CIN + ic0 + 1) * 9 + ktap];
    }
    dst[i] = pack_h2(v0, v1);
}

// ---------------- x channel-last pack (for DCN gather) ----------------
// g_xp[((b*4+g)*HWSZ + pix)*32 + ch] = x[(b*128 + g*32 + ch)*HWSZ + pix]
__global__ void prep_xpack_kernel(const float* __restrict__ x) {
    __shared__ float t[32][129];
    int p0 = blockIdx.x * 128;
    int g  = blockIdx.y;
    int b  = blockIdx.z;
    int tid = threadIdx.x;
    for (int i = tid; i < 32 * 128; i += 256) {
        int ch = i >> 7, px = i & 127;
        t[ch][px] = x[(size_t)(b * CIN + g * 32 + ch) * HWSZ + p0 + px];
    }
    __syncthreads();
    int px = tid >> 1, u = tid & 1;
    float* dst = g_xp + ((size_t)(b * NDG + g) * HWSZ + p0 + px) * 32 + 16 * u;
#pragma unroll
    for (int q = 0; q < 4; q++) {
        float4 v = make_float4(t[16 * u + 4 * q + 0][px], t[16 * u + 4 * q + 1][px],
                               t[16 * u + 4 * q + 2][px], t[16 * u + 4 * q + 3][px]);
        *reinterpret_cast<float4*>(dst + 4 * q) = v;
    }
}

// ---------------- fp16 mma conv3x3 ----------------
// 9 weight buffers, 3 barriers per icc (windows of 4 + 5 taps), credit np <= bc+8.
#define PAIR_S 216
#define NBUF_C 9
#define CONV_SMEM ((8*PAIR_S*2 + NBUF_C*2048) * 4)   // 13824 + 73728 = 87552 B

__device__ __forceinline__ void conv_tap(float cacc[4][4][4], const uint2* stg4,
                                         const uint2* swc4, int koff,
                                         const int pxbase[4], const int rowb[4], int lk) {
#pragma unroll
    for (int s = 0; s < 2; s++) {
        uint32_t A[4][4], B4[4][2];
#pragma unroll
        for (int mt = 0; mt < 4; mt++) {
            int r0 = rowb[mt];
            uint2 u = swc4[r0 * 8 + ((s * 4 + lk + r0) & 7)];
            uint2 v = swc4[(r0 + 8) * 8 + ((s * 4 + lk + r0) & 7)];
            A[mt][0] = u.x; A[mt][1] = v.x; A[mt][2] = u.y; A[mt][3] = v.y;
        }
#pragma unroll
        for (int nt = 0; nt < 4; nt++) {
            uint2 f = stg4[(s * 4 + lk) * PAIR_S + pxbase[nt] + koff];
            B4[nt][0] = f.x; B4[nt][1] = f.y;
        }
#pragma unroll
        for (int mt = 0; mt < 4; mt++)
#pragma unroll
            for (int nt = 0; nt < 4; nt++)
                mma16(cacc[mt][nt], A[mt], B4[nt]);
    }
}

template<int OC, int MODE>
__global__ void __launch_bounds__(256, 2) conv_mma_kernel(const float* __restrict__ xin,
                                                          const float* __restrict__ bias) {
    extern __shared__ float sm[];
    uint2*    stg4 = (uint2*)sm;                       // [8][216]
    uint32_t* swb  = (uint32_t*)(sm + 8 * PAIR_S * 2); // 9 x 2048 u32

    const float*    x   = (MODE == 0) ? xin : g_xres;
    const uint32_t* wAh = (MODE == 0) ? g_wA1h : g_wA2h;
    float*          y   = (MODE == 0) ? g_xres : g_co;

    const int tid = threadIdx.x;
    const int wid = tid >> 5, lane = tid & 31;
    const int warp_m = wid >> 2, warp_n = wid & 3;
    const int lm = lane >> 2, lk = lane & 3;
    const int b = blockIdx.y;
    const int tile_x = (blockIdx.x % 3) * 32;
    const int tile_y = (blockIdx.x / 3) * 4;

    float cacc[4][4][4];
#pragma unroll
    for (int mt = 0; mt < 4; mt++)
#pragma unroll
        for (int nt = 0; nt < 4; nt++)
#pragma unroll
            for (int i = 0; i < 4; i++) cacc[mt][nt][i] = 0.f;

    int pxbase[4], rowb[4];
#pragma unroll
    for (int nt = 0; nt < 4; nt++) {
        int px = warp_n * 32 + nt * 8 + lm;
        pxbase[nt] = (px >> 5) * 34 + (px & 31);
    }
#pragma unroll
    for (int mt = 0; mt < 4; mt++)
        rowb[mt] = warp_m * 64 + mt * 16 + lm;

    const float* xb = x + (size_t)b * CIN * HWSZ;

    int np = 0;
    auto pf = [&](int bc) {
        while (np < 36 && np <= bc + 8) {
            prefetch_w_cp(swb + (np % NBUF_C) * 2048, wAh + (size_t)np * 2048, tid);
            np++;
        }
    };
    pf(0);   // chunks 0..8

    for (int icc = 0; icc < 4; icc++) {
        const int T0 = icc * 9;
        // stage input chunk (stage buffer protected by trailing barrier of prev icc)
        for (int i = tid; i < 8 * 204; i += 256) {
            int g2 = i / 204, rem = i % 204;
            int s = g2 >> 2, lkp = g2 & 3;
            int base = icc * 32 + 16 * s + 2 * lkp;
            int gy = tile_y + rem / 34 - 1, gx = tile_x + rem % 34 - 1;
            float v0 = 0.f, v1 = 0.f, v2 = 0.f, v3 = 0.f;
            if (gy >= 0 && gy < HW && gx >= 0 && gx < HW) {
                const float* p = xb + (size_t)base * HWSZ + gy * HW + gx;
                v0 = p[0]; v1 = p[HWSZ]; v2 = p[8 * HWSZ]; v3 = p[9 * HWSZ];
            }
            uint2 u; u.x = pack_h2(v0, v1); u.y = pack_h2(v2, v3);
            stg4[g2 * PAIR_S + rem] = u;
        }
        CP_WAIT_ALL();
        __syncthreads();          // consumed = T0
        pf(T0);
#pragma unroll
        for (int k = 0; k < 4; k++)
            conv_tap(cacc, stg4, (const uint2*)(swb + ((T0 + k) % NBUF_C) * 2048),
                     (k / 3) * 34 + (k % 3), pxbase, rowb, lk);
        CP_WAIT_ALL();
        __syncthreads();          // consumed = T0+4
        pf(T0 + 4);
#pragma unroll
        for (int k = 4; k < 9; k++)
            conv_tap(cacc, stg4, (const uint2*)(swb + ((T0 + k) % NBUF_C) * 2048),
                     (k / 3) * 34 + (k % 3), pxbase, rowb, lk);
        CP_WAIT_ALL();
        __syncthreads();          // consumed = T0+9 (protects stage rewrite)
    }

    // epilogue
#pragma unroll
    for (int mt = 0; mt < 4; mt++) {
        int oc0 = warp_m * 64 + mt * 16 + lm;
        int oc1 = oc0 + 8;
#pragma unroll
        for (int nt = 0; nt < 4; nt++) {
            int px0 = warp_n * 32 + nt * 8 + lk * 2;
            int gy = tile_y + (px0 >> 5), gx = tile_x + (px0 & 31);
            if (oc0 < OC) {
                float bz = bias[oc0];
                float2 o = make_float2(cacc[mt][nt][0] + bz, cacc[mt][nt][1] + bz);
                *reinterpret_cast<float2*>(&y[((size_t)(b * OC + oc0)) * HWSZ + gy * HW + gx]) = o;
            }
            if (oc1 < OC) {
                float bz = bias[oc1];
                float2 o = make_float2(cacc[mt][nt][2] + bz, cacc[mt][nt][3] + bz);
                *reinterpret_cast<float2*>(&y[((size_t)(b * OC + oc1)) * HWSZ + gy * HW + gx]) = o;
            }
        }
    }
}

// ---------------- modulated deformable conv (fp16 mma, packed-x gather) ----------------
#define COL_S 132
#define COLB32 (8 * COL_S * 2)                    // 2112 u32 per buffer
#define DCN_SMEM ((3*2048 + 2*COLB32) * 4)        // 41472 B

__global__ void __launch_bounds__(256, 2) dcn_mma_kernel(const float* __restrict__ x,
                                                         const float* __restrict__ bias,
                                                         float* __restrict__ y) {
    extern __shared__ float sm[];
    uint32_t* s_w    = (uint32_t*)sm;             // 3 x 2048
    uint32_t* s_colh = s_w + 3 * 2048;            // 2 x 2112

    const int tid = threadIdx.x;
    const int wid = tid >> 5, lane = tid & 31;
    const int warp_m = wid >> 2, warp_n = wid & 3;
    const int lm = lane >> 2, lk = lane & 3;
    const int b = blockIdx.y;
    const int tile_x = (blockIdx.x % 3) * 32;
    const int tile_y = (blockIdx.x / 3) * 4;

    const int px_own = tid & 127;
    const int h      = tid >> 7;                  // channel half
    const int gy_own = tile_y + (px_own >> 5);
    const int gx_own = tile_x + (px_own & 31);

    float cacc[4][4][4];
#pragma unroll
    for (int mt = 0; mt < 4; mt++)
#pragma unroll
        for (int nt = 0; nt < 4; nt++)
#pragma unroll
            for (int i = 0; i < 4; i++) cacc[mt][nt][i] = 0.f;

    int pxidx[4], rowb[4];
#pragma unroll
    for (int nt = 0; nt < 4; nt++)
        pxidx[nt] = warp_n * 32 + nt * 8 + lm;
#pragma unroll
    for (int mt = 0; mt < 4; mt++)
        rowb[mt] = warp_m * 64 + mt * 16 + lm;

    const float* cob = g_co + (size_t)b * OC2 * HWSZ;

    auto phaseA_reg = [&](int idx, int4& iv, float4& wv) {
        int g = idx / 9, k = idx - g * 9;
        int c_y = g * 18 + 2 * k;
        const float* basep = cob + gy_own * HW + gx_own;
        float offy = basep[(size_t)c_y * HWSZ];
        float offx = basep[(size_t)(c_y + 1) * HWSZ];
        float mraw = basep[(size_t)(72 + g * 9 + k) * HWSZ];
        float m  = 1.f / (1.f + __expf(-mraw));
        float ys = (float)gy_own + (float)(k / 3 - 1) + offy;
        float xs = (float)gx_own + (float)(k % 3 - 1) + offx;
        float y0f = floorf(ys), x0f = floorf(xs);
        float fy = ys - y0f, fx = xs - x0f;
        int y0 = (int)y0f, x0 = (int)x0f;
        int idxs[4]; float wgts[4];
#pragma unroll
        for (int cnr = 0; cnr < 4; cnr++) {
            int dy = cnr >> 1, dx = cnr & 1;
            int yi = y0 + dy, xi = x0 + dx;
            bool valid = (yi >= 0) && (yi < HW) && (xi >= 0) && (xi < HW);
            float wy = dy ? fy : (1.f - fy);
            float wx = dx ? fx : (1.f - fx);
            int yc = min(max(yi, 0), HW - 1);
            int xc = min(max(xi, 0), HW - 1);
            idxs[cnr] = yc * HW + xc;
            wgts[cnr] = valid ? (wy * wx * m) : 0.f;
        }
        iv = make_int4(idxs[0], idxs[1], idxs[2], idxs[3]);
        wv = make_float4(wgts[0], wgts[1], wgts[2], wgts[3]);
    };

    auto corner_ld = [&](const float* cp, float v[16]) {
#pragma unroll
        for (int q = 0; q < 4; q++) {
            float4 r = *reinterpret_cast<const float4*>(cp + 4 * q);
            v[4 * q] = r.x; v[4 * q + 1] = r.y; v[4 * q + 2] = r.z; v[4 * q + 3] = r.w;
        }
    };

    auto store_col = [&](int it1, const float acc[16]) {
        uint2* col2 = (uint2*)(s_colh + (it1 & 1) * COLB32);
#pragma unroll
        for (int lkp = 0; lkp < 4; lkp++) {
            col2[(4 * h + lkp) * COL_S + px_own] =
                make_uint2(pack_h2(acc[2 * lkp], acc[2 * lkp + 1]),
                           pack_h2(acc[2 * lkp + 8], acc[2 * lkp + 9]));
        }
    };

    auto do_mma_s = [&](int it, int wslot, int s) {
        const uint2* swc4 = (const uint2*)(s_w + wslot * 2048);
        const uint2* col2 = (const uint2*)(s_colh + (it & 1) * COLB32);
        uint32_t A[4][4], B4[4][2];
#pragma unroll
        for (int mt = 0; mt < 4; mt++) {
            int r0 = rowb[mt];
            uint2 u = swc4[r0 * 8 + ((s * 4 + lk + r0) & 7)];
            uint2 v = swc4[(r0 + 8) * 8 + ((s * 4 + lk + r0) & 7)];
            A[mt][0] = u.x; A[mt][1] = v.x; A[mt][2] = u.y; A[mt][3] = v.y;
        }
#pragma unroll
        for (int nt = 0; nt < 4; nt++) {
            uint2 f = col2[(s * 4 + lk) * COL_S + pxidx[nt]];
            B4[nt][0] = f.x; B4[nt][1] = f.y;
        }
#pragma unroll
        for (int mt = 0; mt < 4; mt++)
#pragma unroll
            for (int nt = 0; nt < 4; nt++)
                mma16(cacc[mt][nt], A[mt], B4[nt]);
    };

    // ---- prologue: tap 0 gather (no MMA yet) ----
    prefetch_w_cp(s_w + 0 * 2048, g_wdh, tid);
    prefetch_w_cp(s_w + 1 * 2048, g_wdh + 2048, tid);
    {
        int4 iv; float4 wv;
        phaseA_reg(0, iv, wv);
        const float* xgp = g_xp + ((size_t)(b * NDG + 0) * HWSZ) * 32 + 16 * h;
        float acc[16], cv[16];
        corner_ld(xgp + (size_t)iv.x * 32, cv);
#pragma unroll
        for (int j = 0; j < 16; j++) acc[j] = wv.x * cv[j];
        corner_ld(xgp + (size_t)iv.y * 32, cv);
#pragma unroll
        for (int j = 0; j < 16; j++) acc[j] = fmaf(wv.y, cv[j], acc[j]);
        corner_ld(xgp + (size_t)iv.z * 32, cv);
#pragma unroll
        for (int j = 0; j < 16; j++) acc[j] = fmaf(wv.z, cv[j], acc[j]);
        corner_ld(xgp + (size_t)iv.w * 32, cv);
#pragma unroll
        for (int j = 0; j < 16; j++) acc[j] = fmaf(wv.w, cv[j], acc[j]);
        store_col(0, acc);
    }

    // ---- main pipeline: 1 barrier per tap; gather(it+1) interleaved with mma(it) ----
    int wslot = 0, pslot = 2;
    for (int it = 0; it < 36; it++) {
        int4 ivn; float4 wvn;
        if (it < 35) phaseA_reg(it + 1, ivn, wvn);
        CP_WAIT_ALL();
        __syncthreads();
        if (it < 34) prefetch_w_cp(s_w + pslot * 2048, g_wdh + (size_t)(it + 2) * 2048, tid);
        if (it < 35) {
            const int gn = (it + 1) / 9;
            const float* xgp = g_xp + ((size_t)(b * NDG + gn) * HWSZ) * 32 + 16 * h;
            float acc[16], cv[16];
            corner_ld(xgp + (size_t)ivn.x * 32, cv);
            do_mma_s(it, wslot, 0);
#pragma unroll
            for (int j = 0; j < 16; j++) acc[j] = wvn.x * cv[j];
            corner_ld(xgp + (size_t)ivn.y * 32, cv);
#pragma unroll
            for (int j = 0; j < 16; j++) acc[j] = fmaf(wvn.y, cv[j], acc[j]);
            corner_ld(xgp + (size_t)ivn.z * 32, cv);
            do_mma_s(it, wslot, 1);
#pragma unroll
            for (int j = 0; j < 16; j++) acc[j] = fmaf(wvn.z, cv[j], acc[j]);
            corner_ld(xgp + (size_t)ivn.w * 32, cv);
#pragma unroll
            for (int j = 0; j < 16; j++) acc[j] = fmaf(wvn.w, cv[j], acc[j]);
            store_col(it + 1, acc);
        } else {
            do_mma_s(it, wslot, 0);
            do_mma_s(it, wslot, 1);
        }
        wslot = (wslot == 2) ? 0 : wslot + 1;
        pslot = (pslot == 2) ? 0 : pslot + 1;
    }

    // epilogue
#pragma unroll
    for (int mt = 0; mt < 4; mt++) {
        int oc0 = warp_m * 64 + mt * 16 + lm;
        int oc1 = oc0 + 8;
        float bz0 = bias[oc0], bz1 = bias[oc1];
#pragma unroll
        for (int nt = 0; nt < 4; nt++) {
            int px0 = warp_n * 32 + nt * 8 + lk * 2;
            int gy = tile_y + (px0 >> 5), gx = tile_x + (px0 & 31);
            *reinterpret_cast<float2*>(&y[((size_t)(b * OC1 + oc0)) * HWSZ + gy * HW + gx]) =
                make_float2(cacc[mt][nt][0] + bz0, cacc[mt][nt][1] + bz0);
            *reinterpret_cast<float2*>(&y[((size_t)(b * OC1 + oc1)) * HWSZ + gy * HW + gx]) =
                make_float2(cacc[mt][nt][2] + bz1, cacc[mt][nt][3] + bz1);
        }
    }
}

// ---------------- launch ----------------
extern "C" void kernel_launch(void* const* d_in, const int* in_sizes, int n_in,
                              void* d_out, int out_size) {
    (void)in_sizes; (void)n_in; (void)out_size;
    const float* x_vq  = (const float*)d_in[0];
    const float* w_off = (const float*)d_in[1];
    const float* b_off = (const float*)d_in[2];
    const float* w_co  = (const float*)d_in[3];
    const float* b_co  = (const float*)d_in[4];
    const float* w_dcn = (const float*)d_in[5];
    const float* b_dcn = (const float*)d_in[6];
    float* out = (float*)d_out;

    cudaFuncSetAttribute(conv_mma_kernel<OC1, 0>, cudaFuncAttributeMaxDynamicSharedMemorySize, CONV_SMEM);
    cudaFuncSetAttribute(conv_mma_kernel<OC2, 1>, cudaFuncAttributeMaxDynamicSharedMemorySize, CONV_SMEM);
    cudaFuncSetAttribute(dcn_mma_kernel, cudaFuncAttributeMaxDynamicSharedMemorySize, DCN_SMEM);

    prep_wh_kernel<<<288, 256>>>(w_off, OC1, 0);
    prep_wh_kernel<<<288, 256>>>(w_co,  OC2, 1);
    prep_wh_kernel<<<288, 256>>>(w_dcn, OC1, 2);
    {
        dim3 xg(HWSZ / 128, NDG, BATCH);
        prep_xpack_kernel<<<xg, 256>>>(x_vq);
    }

    dim3 cgrid(72, BATCH);   // 3x24 tiles of 32x4 px, 128 oc per CTA
    conv_mma_kernel<OC1, 0><<<cgrid, 256, CONV_SMEM>>>(x_vq, b_off);
    conv_mma_kernel<OC2, 1><<<cgrid, 256, CONV_SMEM>>>(nullptr, b_co);

    dim3 dgrid(72, BATCH);
    dcn_mma_kernel<<<dgrid, 256, DCN_SMEM>>>(x_vq, b_dcn, out);
}

// round 14
// speedup vs baseline: 1.6375x; 1.6375x over previous
#include <cuda_runtime.h>
#include <cuda_fp16.h>
#include <cstdint>

#define CIN   128
#define HW    96
#define HWSZ  9216
#define BATCH 4
#define OC1   128
#define OC2   108
#define NDG   4

// ---------------- scratch (static device globals; no allocs) ----------------
__device__ float    g_xres[BATCH * OC1 * HWSZ];  // conv1 output
__device__ float    g_co  [BATCH * OC2 * HWSZ];  // conv2 output
__device__ uint32_t g_xh  [BATCH * 64 * HWSZ];   // x as half2 pairs: [b][g*16+cp][pix]
// fp16 weights, group-packed + rotation-swizzled: [chunk][oc][slot(8)][hl(2)] u32=half2
__device__ uint32_t g_wA1h[36 * 128 * 16];
__device__ uint32_t g_wA2h[36 * 128 * 16];
__device__ uint32_t g_wdh [36 * 128 * 16];

// ---------------- helpers ----------------
__device__ __forceinline__ void mma16(float c[4], const uint32_t a[4], const uint32_t b[2]) {
    asm volatile("mma.sync.aligned.m16n8k16.row.col.f32.f16.f16.f32 "
        "{%0,%1,%2,%3}, {%4,%5,%6,%7}, {%8,%9}, {%0,%1,%2,%3};"
        : "+f"(c[0]), "+f"(c[1]), "+f"(c[2]), "+f"(c[3])
        : "r"(a[0]), "r"(a[1]), "r"(a[2]), "r"(a[3]), "r"(b[0]), "r"(b[1]));
}
__device__ __forceinline__ uint32_t pack_h2(float a, float b) {
    __half2 h = __floats2half2_rn(a, b);
    return *reinterpret_cast<uint32_t*>(&h);
}
__device__ __forceinline__ uint32_t smem_u32(const void* p) {
    return (uint32_t)__cvta_generic_to_shared(p);
}
__device__ __forceinline__ void cp_async16(uint32_t saddr, const void* g) {
    asm volatile("cp.async.cg.shared.global [%0], [%1], 16;" :: "r"(saddr), "l"(g));
}
#define CP_WAIT_ALL() asm volatile("cp.async.wait_all;" ::: "memory")

// async copy of one 8KB weight chunk (2048 u32, flat)
__device__ __forceinline__ void prefetch_w_cp(uint32_t* dst, const uint32_t* src, int tid) {
    uint32_t base = smem_u32(dst);
#pragma unroll
    for (int j = 0; j < 2; j++) {
        int t4 = tid + j * 256;
        cp_async16(base + t4 * 16, src + t4 * 4);
    }
}

// ---------------- weight prep (conv1 + conv2 + dcn in ONE launch) ----------------
__global__ void prep_wh_kernel(const float* __restrict__ w0, const float* __restrict__ w1,
                               const float* __restrict__ w2) {
    int which = blockIdx.x / 288;
    int i = (blockIdx.x % 288) * 256 + threadIdx.x;
    if (i >= 36 * 128 * 16) return;
    const float* w = (which == 0) ? w0 : (which == 1) ? w1 : w2;
    uint32_t* dst  = (which == 0) ? g_wA1h : (which == 1) ? g_wA2h : g_wdh;
    int OC = (which == 1) ? OC2 : OC1;
    int j = i & 15, oc = (i >> 4) & 127, chunk = i >> 11;
    int slot = j >> 1, hl = j & 1;
    int g2 = (slot - oc) & 7;
    int s = g2 >> 2, lkp = g2 & 3;
    int kb = 16 * s + 2 * lkp + 8 * hl;
    int grp = chunk / 9, ktap = chunk % 9;
    int ic0 = grp * 32 + kb;
    float v0 = 0.f, v1 = 0.f;
    if (oc < OC) {
        v0 = w[(oc * CIN + ic0) * 9 + ktap];
        v1 = w[(oc * CIN + ic0 + 1) * 9 + ktap];
    }
    dst[i] = pack_h2(v0, v1);
}

// ---------------- x fp16 channel-pair pack (pixel-major; gather stays coalesced) ----
__global__ void prep_xh_kernel(const float* __restrict__ x) {
    int i = blockIdx.x * 256 + threadIdx.x;
    if (i >= BATCH * 64 * HWSZ) return;
    int p = i % HWSZ, c2 = (i / HWSZ) & 63, b = i / (HWSZ * 64);
    float v0 = x[((size_t)(b * CIN + 2 * c2)) * HWSZ + p];
    float v1 = x[((size_t)(b * CIN + 2 * c2 + 1)) * HWSZ + p];
    g_xh[i] = pack_h2(v0, v1);
}

// ---------------- fp16 mma conv3x3 (bit-exact R12) ----------------
#define PAIR_S 216
#define CONV_SMEM ((8*PAIR_S*2 + 4*2048) * 4)   // 46592 B

__device__ __forceinline__ void conv_tap(float cacc[4][4][4], const uint2* stg4,
                                         const uint2* swc4, int koff,
                                         const int pxbase[4], const int rowb[4], int lk) {
#pragma unroll
    for (int s = 0; s < 2; s++) {
        uint32_t A[4][4], B4[4][2];
#pragma unroll
        for (int mt = 0; mt < 4; mt++) {
            int r0 = rowb[mt];
            uint2 u = swc4[r0 * 8 + ((s * 4 + lk + r0) & 7)];
            uint2 v = swc4[(r0 + 8) * 8 + ((s * 4 + lk + r0) & 7)];
            A[mt][0] = u.x; A[mt][1] = v.x; A[mt][2] = u.y; A[mt][3] = v.y;
        }
#pragma unroll
        for (int nt = 0; nt < 4; nt++) {
            uint2 f = stg4[(s * 4 + lk) * PAIR_S + pxbase[nt] + koff];
            B4[nt][0] = f.x; B4[nt][1] = f.y;
        }
#pragma unroll
        for (int mt = 0; mt < 4; mt++)
#pragma unroll
            for (int nt = 0; nt < 4; nt++)
                mma16(cacc[mt][nt], A[mt], B4[nt]);
    }
}

template<int OC, int MODE>
__global__ void __launch_bounds__(256, 2) conv_mma_kernel(const float* __restrict__ xin,
                                                          const float* __restrict__ bias) {
    extern __shared__ float sm[];
    uint2*    stg4 = (uint2*)sm;                       // [8][216]
    uint32_t* swb  = (uint32_t*)(sm + 8 * PAIR_S * 2); // 4 x 2048 u32

    const float*    x   = (MODE == 0) ? xin : g_xres;
    const uint32_t* wAh = (MODE == 0) ? g_wA1h : g_wA2h;
    float*          y   = (MODE == 0) ? g_xres : g_co;

    const int tid = threadIdx.x;
    const int wid = tid >> 5, lane = tid & 31;
    const int warp_m = wid >> 2, warp_n = wid & 3;
    const int lm = lane >> 2, lk = lane & 3;
    const int b = blockIdx.y;
    const int tile_x = (blockIdx.x % 3) * 32;
    const int tile_y = (blockIdx.x / 3) * 4;

    float cacc[4][4][4];
#pragma unroll
    for (int mt = 0; mt < 4; mt++)
#pragma unroll
        for (int nt = 0; nt < 4; nt++)
#pragma unroll
            for (int i = 0; i < 4; i++) cacc[mt][nt][i] = 0.f;

    int pxbase[4], rowb[4];
#pragma unroll
    for (int nt = 0; nt < 4; nt++) {
        int px = warp_n * 32 + nt * 8 + lm;
        pxbase[nt] = (px >> 5) * 34 + (px & 31);
    }
#pragma unroll
    for (int mt = 0; mt < 4; mt++)
        rowb[mt] = warp_m * 64 + mt * 16 + lm;

    const float* xb = x + (size_t)b * CIN * HWSZ;

    prefetch_w_cp(swb + 0 * 2048, wAh, tid);
    prefetch_w_cp(swb + 1 * 2048, wAh + 2048, tid);

    int np = 2, c = 0;
    for (int icc = 0; icc < 4; icc++) {
        for (int i = tid; i < 8 * 204; i += 256) {
            int g2 = i / 204, rem = i % 204;
            int s = g2 >> 2, lkp = g2 & 3;
            int base = icc * 32 + 16 * s + 2 * lkp;
            int gy = tile_y + rem / 34 - 1, gx = tile_x + rem % 34 - 1;
            float v0 = 0.f, v1 = 0.f, v2 = 0.f, v3 = 0.f;
            if (gy >= 0 && gy < HW && gx >= 0 && gx < HW) {
                const float* p = xb + (size_t)base * HWSZ + gy * HW + gx;
                v0 = p[0]; v1 = p[HWSZ]; v2 = p[8 * HWSZ]; v3 = p[9 * HWSZ];
            }
            uint2 u; u.x = pack_h2(v0, v1); u.y = pack_h2(v2, v3);
            stg4[g2 * PAIR_S + rem] = u;
        }
        CP_WAIT_ALL();
        __syncthreads();

        for (int k0 = 0; k0 < 9; k0 += 2) {
#pragma unroll
            for (int t = 0; t < 2; t++) {
                if (np <= c + 3 && np < 36) {
                    prefetch_w_cp(swb + (np & 3) * 2048, wAh + (size_t)np * 2048, tid);
                    np++;
                }
            }
            {
                const int k = k0;
                conv_tap(cacc, stg4, (const uint2*)(swb + (c & 3) * 2048),
                         (k / 3) * 34 + (k % 3), pxbase, rowb, lk);
            }
            if (k0 < 8) {
                const int k = k0 + 1;
                conv_tap(cacc, stg4, (const uint2*)(swb + ((c + 1) & 3) * 2048),
                         (k / 3) * 34 + (k % 3), pxbase, rowb, lk);
                c += 2;
            } else {
                c += 1;
            }
            CP_WAIT_ALL();
            __syncthreads();
        }
    }

    // epilogue
#pragma unroll
    for (int mt = 0; mt < 4; mt++) {
        int oc0 = warp_m * 64 + mt * 16 + lm;
        int oc1 = oc0 + 8;
#pragma unroll
        for (int nt = 0; nt < 4; nt++) {
            int px0 = warp_n * 32 + nt * 8 + lk * 2;
            int gy = tile_y + (px0 >> 5), gx = tile_x + (px0 & 31);
            if (oc0 < OC) {
                float bz = bias[oc0];
                float2 o = make_float2(cacc[mt][nt][0] + bz, cacc[mt][nt][1] + bz);
                *reinterpret_cast<float2*>(&y[((size_t)(b * OC + oc0)) * HWSZ + gy * HW + gx]) = o;
            }
            if (oc1 < OC) {
                float bz = bias[oc1];
                float2 o = make_float2(cacc[mt][nt][2] + bz, cacc[mt][nt][3] + bz);
                *reinterpret_cast<float2*>(&y[((size_t)(b * OC + oc1)) * HWSZ + gy * HW + gx]) = o;
            }
        }
    }
}

// ---------------- modulated deformable conv (fp16 mma, half2 channel-pair gather) ----
#define COL_S 132
#define COLB32 (8 * COL_S * 2)                    // 2112 u32 per buffer
#define DCN_SMEM ((3*2048 + 2*COLB32) * 4)        // 41472 B

__global__ void __launch_bounds__(256, 2) dcn_mma_kernel(const float* __restrict__ bias,
                                                         float* __restrict__ y) {
    extern __shared__ float sm[];
    uint32_t* s_w    = (uint32_t*)sm;             // 3 x 2048
    uint32_t* s_colh = s_w + 3 * 2048;            // 2 x 2112

    const int tid = threadIdx.x;
    const int wid = tid >> 5, lane = tid & 31;
    const int warp_m = wid >> 2, warp_n = wid & 3;
    const int lm = lane >> 2, lk = lane & 3;
    const int b = blockIdx.y;
    const int tile_x = (blockIdx.x % 3) * 32;
    const int tile_y = (blockIdx.x / 3) * 4;

    const int px_own = tid & 127;
    const int h      = tid >> 7;                  // channel half: cpairs 8h..8h+7
    const int gy_own = tile_y + (px_own >> 5);
    const int gx_own = tile_x + (px_own & 31);

    float cacc[4][4][4];
#pragma unroll
    for (int mt = 0; mt < 4; mt++)
#pragma unroll
        for (int nt = 0; nt < 4; nt++)
#pragma unroll
            for (int i = 0; i < 4; i++) cacc[mt][nt][i] = 0.f;

    int pxidx[4], rowb[4];
#pragma unroll
    for (int nt = 0; nt < 4; nt++)
        pxidx[nt] = warp_n * 32 + nt * 8 + lm;
#pragma unroll
    for (int mt = 0; mt < 4; mt++)
        rowb[mt] = warp_m * 64 + mt * 16 + lm;

    const float* cob = g_co + (size_t)b * OC2 * HWSZ;

    auto phaseA_reg = [&](int idx, int4& iv, float4& wv) {
        int g = idx / 9, k = idx - g * 9;
        int c_y = g * 18 + 2 * k;
        const float* basep = cob + gy_own * HW + gx_own;
        float offy = basep[(size_t)c_y * HWSZ];
        float offx = basep[(size_t)(c_y + 1) * HWSZ];
        float mraw = basep[(size_t)(72 + g * 9 + k) * HWSZ];
        float m  = 1.f / (1.f + __expf(-mraw));
        float ys = (float)gy_own + (float)(k / 3 - 1) + offy;
        float xs = (float)gx_own + (float)(k % 3 - 1) + offx;
        float y0f = floorf(ys), x0f = floorf(xs);
        float fy = ys - y0f, fx = xs - x0f;
        int y0 = (int)y0f, x0 = (int)x0f;
        int idxs[4]; float wgts[4];
#pragma unroll
        for (int cnr = 0; cnr < 4; cnr++) {
            int dy = cnr >> 1, dx = cnr & 1;
            int yi = y0 + dy, xi = x0 + dx;
            bool valid = (yi >= 0) && (yi < HW) && (xi >= 0) && (xi < HW);
            float wy = dy ? fy : (1.f - fy);
            float wx = dx ? fx : (1.f - fx);
            int yc = min(max(yi, 0), HW - 1);
            int xc = min(max(xi, 0), HW - 1);
            idxs[cnr] = yc * HW + xc;
            wgts[cnr] = valid ? (wy * wx * m) : 0.f;
        }
        iv = make_int4(idxs[0], idxs[1], idxs[2], idxs[3]);
        wv = make_float4(wgts[0], wgts[1], wgts[2], wgts[3]);
    };

    // one corner: 8 half2 channel-pair loads (coalesced: neighboring px -> +4B)
    auto corner_ld = [&](const uint32_t* xgp, int piv, float v[16]) {
#pragma unroll
        for (int cp = 0; cp < 8; cp++) {
            uint32_t u = __ldg(xgp + (size_t)cp * HWSZ + piv);
            __half2 hh = *reinterpret_cast<__half2*>(&u);
            float2 f = __half22float2(hh);
            v[2 * cp] = f.x; v[2 * cp + 1] = f.y;
        }
    };

    auto store_col = [&](int it1, const float acc[16]) {
        uint2* col2 = (uint2*)(s_colh + (it1 & 1) * COLB32);
#pragma unroll
        for (int lkp = 0; lkp < 4; lkp++) {
            col2[(4 * h + lkp) * COL_S + px_own] =
                make_uint2(pack_h2(acc[2 * lkp], acc[2 * lkp + 1]),
                           pack_h2(acc[2 * lkp + 8], acc[2 * lkp + 9]));
        }
    };

    auto do_mma_s = [&](int it, int wslot, int s) {
        const uint2* swc4 = (const uint2*)(s_w + wslot * 2048);
        const uint2* col2 = (const uint2*)(s_colh + (it & 1) * COLB32);
        uint32_t A[4][4], B4[4][2];
#pragma unroll
        for (int mt = 0; mt < 4; mt++) {
            int r0 = rowb[mt];
            uint2 u = swc4[r0 * 8 + ((s * 4 + lk + r0) & 7)];
            uint2 v = swc4[(r0 + 8) * 8 + ((s * 4 + lk + r0) & 7)];
            A[mt][0] = u.x; A[mt][1] = v.x; A[mt][2] = u.y; A[mt][3] = v.y;
        }
#pragma unroll
        for (int nt = 0; nt < 4; nt++) {
            uint2 f = col2[(s * 4 + lk) * COL_S + pxidx[nt]];
            B4[nt][0] = f.x; B4[nt][1] = f.y;
        }
#pragma unroll
        for (int mt = 0; mt < 4; mt++)
#pragma unroll
            for (int nt = 0; nt < 4; nt++)
                mma16(cacc[mt][nt], A[mt], B4[nt]);
    };

    // ---- prologue: tap 0 gather ----
    prefetch_w_cp(s_w + 0 * 2048, g_wdh, tid);
    prefetch_w_cp(s_w + 1 * 2048, g_wdh + 2048, tid);
    {
        int4 iv; float4 wv;
        phaseA_reg(0, iv, wv);
        const uint32_t* xgp = g_xh + ((size_t)(b * NDG + 0) * 16 + 8 * h) * HWSZ;
        float acc[16], cv[16];
        corner_ld(xgp, iv.x, cv);
#pragma unroll
        for (int j = 0; j < 16; j++) acc[j] = wv.x * cv[j];
        corner_ld(xgp, iv.y, cv);
#pragma unroll
        for (int j = 0; j < 16; j++) acc[j] = fmaf(wv.y, cv[j], acc[j]);
        corner_ld(xgp, iv.z, cv);
#pragma unroll
        for (int j = 0; j < 16; j++) acc[j] = fmaf(wv.z, cv[j], acc[j]);
        corner_ld(xgp, iv.w, cv);
#pragma unroll
        for (int j = 0; j < 16; j++) acc[j] = fmaf(wv.w, cv[j], acc[j]);
        store_col(0, acc);
    }

    // ---- main pipeline: 1 barrier per tap; gather(it+1) interleaved with mma(it) ----
    int wslot = 0, pslot = 2;
    for (int it = 0; it < 36; it++) {
        int4 ivn; float4 wvn;
        if (it < 35) phaseA_reg(it + 1, ivn, wvn);
        CP_WAIT_ALL();
        __syncthreads();
        if (it < 34) prefetch_w_cp(s_w + pslot * 2048, g_wdh + (size_t)(it + 2) * 2048, tid);
        if (it < 35) {
            const int gn = (it + 1) / 9;
            const uint32_t* xgp = g_xh + ((size_t)(b * NDG + gn) * 16 + 8 * h) * HWSZ;
            float acc[16], cv[16];
            corner_ld(xgp, ivn.x, cv);
            do_mma_s(it, wslot, 0);
#pragma unroll
            for (int j = 0; j < 16; j++) acc[j] = wvn.x * cv[j];
            corner_ld(xgp, ivn.y, cv);
#pragma unroll
            for (int j = 0; j < 16; j++) acc[j] = fmaf(wvn.y, cv[j], acc[j]);
            corner_ld(xgp, ivn.z, cv);
            do_mma_s(it, wslot, 1);
#pragma unroll
            for (int j = 0; j < 16; j++) acc[j] = fmaf(wvn.z, cv[j], acc[j]);
            corner_ld(xgp, ivn.w, cv);
#pragma unroll
            for (int j = 0; j < 16; j++) acc[j] = fmaf(wvn.w, cv[j], acc[j]);
            store_col(it + 1, acc);
        } else {
            do_mma_s(it, wslot, 0);
            do_mma_s(it, wslot, 1);
        }
        wslot = (wslot == 2) ? 0 : wslot + 1;
        pslot = (pslot == 2) ? 0 : pslot + 1;
    }

    // epilogue
#pragma unroll
    for (int mt = 0; mt < 4; mt++) {
        int oc0 = warp_m * 64 + mt * 16 + lm;
        int oc1 = oc0 + 8;
        float bz0 = bias[oc0], bz1 = bias[oc1];
#pragma unroll
        for (int nt = 0; nt < 4; nt++) {
            int px0 = warp_n * 32 + nt * 8 + lk * 2;
            int gy = tile_y + (px0 >> 5), gx = tile_x + (px0 & 31);
            *reinterpret_cast<float2*>(&y[((size_t)(b * OC1 + oc0)) * HWSZ + gy * HW + gx]) =
                make_float2(cacc[mt][nt][0] + bz0, cacc[mt][nt][1] + bz0);
            *reinterpret_cast<float2*>(&y[((size_t)(b * OC1 + oc1)) * HWSZ + gy * HW + gx]) =
                make_float2(cacc[mt][nt][2] + bz1, cacc[mt][nt][3] + bz1);
        }
    }
}

// ---------------- launch ----------------
extern "C" void kernel_launch(void* const* d_in, const int* in_sizes, int n_in,
                              void* d_out, int out_size) {
    (void)in_sizes; (void)n_in; (void)out_size;
    const float* x_vq  = (const float*)d_in[0];
    const float* w_off = (const float*)d_in[1];
    const float* b_off = (const float*)d_in[2];
    const float* w_co  = (const float*)d_in[3];
    const float* b_co  = (const float*)d_in[4];
    const float* w_dcn = (const float*)d_in[5];
    const float* b_dcn = (const float*)d_in[6];
    float* out = (float*)d_out;

    cudaFuncSetAttribute(conv_mma_kernel<OC1, 0>, cudaFuncAttributeMaxDynamicSharedMemorySize, CONV_SMEM);
    cudaFuncSetAttribute(conv_mma_kernel<OC2, 1>, cudaFuncAttributeMaxDynamicSharedMemorySize, CONV_SMEM);
    cudaFuncSetAttribute(dcn_mma_kernel, cudaFuncAttributeMaxDynamicSharedMemorySize, DCN_SMEM);

    prep_wh_kernel<<<864, 256>>>(w_off, w_co, w_dcn);
    prep_xh_kernel<<<(BATCH * 64 * HWSZ + 255) / 256, 256>>>(x_vq);

    dim3 cgrid(72, BATCH);   // 3x24 tiles of 32x4 px, 128 oc per CTA
    conv_mma_kernel<OC1, 0><<<cgrid, 256, CONV_SMEM>>>(x_vq, b_off);
    conv_mma_kernel<OC2, 1><<<cgrid, 256, CONV_SMEM>>>(nullptr, b_co);

    dim3 dgrid(72, BATCH);
    dcn_mma_kernel<<<dgrid, 256, DCN_SMEM>>>(b_dcn, out);
}

// round 15
// speedup vs baseline: 1.6907x; 1.0324x over previous
#include <cuda_runtime.h>
#include <cuda_fp16.h>
#include <cstdint>

#define CIN   128
#define HW    96
#define HWSZ  9216
#define BATCH 4
#define OC1   128
#define OC2   108
#define NDG   4

// ---------------- scratch (static device globals; no allocs) ----------------
__device__ float    g_co  [BATCH * OC2 * HWSZ];  // conv2 output (fp32, DCN phaseA reads it)
__device__ uint32_t g_xh  [BATCH * 64 * HWSZ];   // x as half2 pairs: [b][cp][pix]
__device__ uint32_t g_x1h [BATCH * 64 * HWSZ];   // conv1 out as half2 pairs: [b][cp][pix]
// fp16 weights, group-packed + rotation-swizzled: [chunk][oc][slot(8)][hl(2)] u32=half2
__device__ uint32_t g_wA1h[36 * 128 * 16];
__device__ uint32_t g_wA2h[36 * 128 * 16];
__device__ uint32_t g_wdh [36 * 128 * 16];

// ---------------- helpers ----------------
__device__ __forceinline__ void mma16(float c[4], const uint32_t a[4], const uint32_t b[2]) {
    asm volatile("mma.sync.aligned.m16n8k16.row.col.f32.f16.f16.f32 "
        "{%0,%1,%2,%3}, {%4,%5,%6,%7}, {%8,%9}, {%0,%1,%2,%3};"
        : "+f"(c[0]), "+f"(c[1]), "+f"(c[2]), "+f"(c[3])
        : "r"(a[0]), "r"(a[1]), "r"(a[2]), "r"(a[3]), "r"(b[0]), "r"(b[1]));
}
__device__ __forceinline__ uint32_t pack_h2(float a, float b) {
    __half2 h = __floats2half2_rn(a, b);
    return *reinterpret_cast<uint32_t*>(&h);
}
__device__ __forceinline__ uint32_t smem_u32(const void* p) {
    return (uint32_t)__cvta_generic_to_shared(p);
}
__device__ __forceinline__ void cp_async16(uint32_t saddr, const void* g) {
    asm volatile("cp.async.cg.shared.global [%0], [%1], 16;" :: "r"(saddr), "l"(g));
}
#define CP_WAIT_ALL() asm volatile("cp.async.wait_all;" ::: "memory")

// async copy of one 8KB weight chunk (2048 u32, flat)
__device__ __forceinline__ void prefetch_w_cp(uint32_t* dst, const uint32_t* src, int tid) {
    uint32_t base = smem_u32(dst);
#pragma unroll
    for (int j = 0; j < 2; j++) {
        int t4 = tid + j * 256;
        cp_async16(base + t4 * 16, src + t4 * 4);
    }
}

// ---------------- weight prep (conv1 + conv2 + dcn in ONE launch) ----------------
__global__ void prep_wh_kernel(const float* __restrict__ w0, const float* __restrict__ w1,
                               const float* __restrict__ w2) {
    int which = blockIdx.x / 288;
    int i = (blockIdx.x % 288) * 256 + threadIdx.x;
    if (i >= 36 * 128 * 16) return;
    const float* w = (which == 0) ? w0 : (which == 1) ? w1 : w2;
    uint32_t* dst  = (which == 0) ? g_wA1h : (which == 1) ? g_wA2h : g_wdh;
    int OC = (which == 1) ? OC2 : OC1;
    int j = i & 15, oc = (i >> 4) & 127, chunk = i >> 11;
    int slot = j >> 1, hl = j & 1;
    int g2 = (slot - oc) & 7;
    int s = g2 >> 2, lkp = g2 & 3;
    int kb = 16 * s + 2 * lkp + 8 * hl;
    int grp = chunk / 9, ktap = chunk % 9;
    int ic0 = grp * 32 + kb;
    float v0 = 0.f, v1 = 0.f;
    if (oc < OC) {
        v0 = w[(oc * CIN + ic0) * 9 + ktap];
        v1 = w[(oc * CIN + ic0 + 1) * 9 + ktap];
    }
    dst[i] = pack_h2(v0, v1);
}

// ---------------- x fp16 channel-pair pack ----------------
__global__ void prep_xh_kernel(const float* __restrict__ x) {
    int i = blockIdx.x * 256 + threadIdx.x;
    if (i >= BATCH * 64 * HWSZ) return;
    int p = i % HWSZ, c2 = (i / HWSZ) & 63, b = i / (HWSZ * 64);
    float v0 = x[((size_t)(b * CIN + 2 * c2)) * HWSZ + p];
    float v1 = x[((size_t)(b * CIN + 2 * c2 + 1)) * HWSZ + p];
    g_xh[i] = pack_h2(v0, v1);
}

// ---------------- fp16 mma conv3x3 ----------------
// Staging now reads half2 pair-planes directly (g_xh / g_x1h): 2 LDG.32, no cvt.
// MODE 0 epilogue writes fp16 pair-planes g_x1h via shuffle pairing (half bytes).
#define PAIR_S 216
#define CONV_SMEM ((8*PAIR_S*2 + 4*2048) * 4)   // 46592 B

__device__ __forceinline__ void conv_tap(float cacc[4][4][4], const uint2* stg4,
                                         const uint2* swc4, int koff,
                                         const int pxbase[4], const int rowb[4], int lk) {
#pragma unroll
    for (int s = 0; s < 2; s++) {
        uint32_t A[4][4], B4[4][2];
#pragma unroll
        for (int mt = 0; mt < 4; mt++) {
            int r0 = rowb[mt];
            uint2 u = swc4[r0 * 8 + ((s * 4 + lk + r0) & 7)];
            uint2 v = swc4[(r0 + 8) * 8 + ((s * 4 + lk + r0) & 7)];
            A[mt][0] = u.x; A[mt][1] = v.x; A[mt][2] = u.y; A[mt][3] = v.y;
        }
#pragma unroll
        for (int nt = 0; nt < 4; nt++) {
            uint2 f = stg4[(s * 4 + lk) * PAIR_S + pxbase[nt] + koff];
            B4[nt][0] = f.x; B4[nt][1] = f.y;
        }
#pragma unroll
        for (int mt = 0; mt < 4; mt++)
#pragma unroll
            for (int nt = 0; nt < 4; nt++)
                mma16(cacc[mt][nt], A[mt], B4[nt]);
    }
}

template<int OC, int MODE>
__global__ void __launch_bounds__(256, 2) conv_mma_kernel(const float* __restrict__ bias) {
    extern __shared__ float sm[];
    uint2*    stg4 = (uint2*)sm;                       // [8][216]
    uint32_t* swb  = (uint32_t*)(sm + 8 * PAIR_S * 2); // 4 x 2048 u32

    const uint32_t* xph = (MODE == 0) ? g_xh : g_x1h;
    const uint32_t* wAh = (MODE == 0) ? g_wA1h : g_wA2h;

    const int tid = threadIdx.x;
    const int wid = tid >> 5, lane = tid & 31;
    const int warp_m = wid >> 2, warp_n = wid & 3;
    const int lm = lane >> 2, lk = lane & 3;
    const int b = blockIdx.y;
    const int tile_x = (blockIdx.x % 3) * 32;
    const int tile_y = (blockIdx.x / 3) * 4;

    float cacc[4][4][4];
#pragma unroll
    for (int mt = 0; mt < 4; mt++)
#pragma unroll
        for (int nt = 0; nt < 4; nt++)
#pragma unroll
            for (int i = 0; i < 4; i++) cacc[mt][nt][i] = 0.f;

    int pxbase[4], rowb[4];
#pragma unroll
    for (int nt = 0; nt < 4; nt++) {
        int px = warp_n * 32 + nt * 8 + lm;
        pxbase[nt] = (px >> 5) * 34 + (px & 31);
    }
#pragma unroll
    for (int mt = 0; mt < 4; mt++)
        rowb[mt] = warp_m * 64 + mt * 16 + lm;

    const uint32_t* xpb = xph + (size_t)b * 64 * HWSZ;

    prefetch_w_cp(swb + 0 * 2048, wAh, tid);
    prefetch_w_cp(swb + 1 * 2048, wAh + 2048, tid);

    int np = 2, c = 0;
    for (int icc = 0; icc < 4; icc++) {
        // stage input chunk straight from half2 pair-planes (no conversion)
        for (int i = tid; i < 8 * 204; i += 256) {
            int g2 = i / 204, rem = i % 204;
            int s = g2 >> 2, lkp = g2 & 3;
            int cp0 = icc * 16 + 8 * s + lkp;
            int gy = tile_y + rem / 34 - 1, gx = tile_x + rem % 34 - 1;
            uint32_t ux = 0u, uy = 0u;
            if (gy >= 0 && gy < HW && gx >= 0 && gx < HW) {
                const uint32_t* p = xpb + (size_t)cp0 * HWSZ + gy * HW + gx;
                ux = __ldg(p);
                uy = __ldg(p + 4 * HWSZ);
            }
            stg4[g2 * PAIR_S + rem] = make_uint2(ux, uy);
        }
        CP_WAIT_ALL();
        __syncthreads();

        for (int k0 = 0; k0 < 9; k0 += 2) {
#pragma unroll
            for (int t = 0; t < 2; t++) {
                if (np <= c + 3 && np < 36) {
                    prefetch_w_cp(swb + (np & 3) * 2048, wAh + (size_t)np * 2048, tid);
                    np++;
                }
            }
            {
                const int k = k0;
                conv_tap(cacc, stg4, (const uint2*)(swb + (c & 3) * 2048),
                         (k / 3) * 34 + (k % 3), pxbase, rowb, lk);
            }
            if (k0 < 8) {
                const int k = k0 + 1;
                conv_tap(cacc, stg4, (const uint2*)(swb + ((c + 1) & 3) * 2048),
                         (k / 3) * 34 + (k % 3), pxbase, rowb, lk);
                c += 2;
            } else {
                c += 1;
            }
            CP_WAIT_ALL();
            __syncthreads();
        }
    }

    // epilogue
    if (MODE == 0) {
        // write fp16 pair-planes: shuffle-pair adjacent oc (lm, lm+1), even lm stores
#pragma unroll
        for (int mt = 0; mt < 4; mt++) {
            int oc0 = warp_m * 64 + mt * 16 + lm;
            float bz0 = bias[oc0], bz1 = bias[oc0 + 8];
#pragma unroll
            for (int nt = 0; nt < 4; nt++) {
                float v0 = cacc[mt][nt][0] + bz0, v1 = cacc[mt][nt][1] + bz0;
                float v2 = cacc[mt][nt][2] + bz1, v3 = cacc[mt][nt][3] + bz1;
                float q0 = __shfl_down_sync(0xFFFFFFFFu, v0, 4);
                float q1 = __shfl_down_sync(0xFFFFFFFFu, v1, 4);
                float q2 = __shfl_down_sync(0xFFFFFFFFu, v2, 4);
                float q3 = __shfl_down_sync(0xFFFFFFFFu, v3, 4);
                if (!(lm & 1)) {
                    int px0 = warp_n * 32 + nt * 8 + lk * 2;
                    int gy = tile_y + (px0 >> 5), gx = tile_x + (px0 & 31);
                    int cpa = warp_m * 32 + mt * 8 + (lm >> 1);
                    uint32_t* d0 = g_x1h + ((size_t)(b * 64 + cpa)) * HWSZ + gy * HW + gx;
                    *reinterpret_cast<uint2*>(d0) = make_uint2(pack_h2(v0, q0), pack_h2(v1, q1));
                    uint32_t* d1 = g_x1h + ((size_t)(b * 64 + cpa + 4)) * HWSZ + gy * HW + gx;
                    *reinterpret_cast<uint2*>(d1) = make_uint2(pack_h2(v2, q2), pack_h2(v3, q3));
                }
            }
        }
    } else {
#pragma unroll
        for (int mt = 0; mt < 4; mt++) {
            int oc0 = warp_m * 64 + mt * 16 + lm;
            int oc1 = oc0 + 8;
#pragma unroll
            for (int nt = 0; nt < 4; nt++) {
                int px0 = warp_n * 32 + nt * 8 + lk * 2;
                int gy = tile_y + (px0 >> 5), gx = tile_x + (px0 & 31);
                if (oc0 < OC) {
                    float bz = bias[oc0];
                    float2 o = make_float2(cacc[mt][nt][0] + bz, cacc[mt][nt][1] + bz);
                    *reinterpret_cast<float2*>(&g_co[((size_t)(b * OC + oc0)) * HWSZ + gy * HW + gx]) = o;
                }
                if (oc1 < OC) {
                    float bz = bias[oc1];
                    float2 o = make_float2(cacc[mt][nt][2] + bz, cacc[mt][nt][3] + bz);
                    *reinterpret_cast<float2*>(&g_co[((size_t)(b * OC + oc1)) * HWSZ + gy * HW + gx]) = o;
                }
            }
        }
    }
}

// ---------------- modulated deformable conv (unchanged from R14 measured-good) ----
#define COL_S 132
#define COLB32 (8 * COL_S * 2)                    // 2112 u32 per buffer
#define DCN_SMEM ((3*2048 + 2*COLB32) * 4)        // 41472 B

__global__ void __launch_bounds__(256, 2) dcn_mma_kernel(const float* __restrict__ bias,
                                                         float* __restrict__ y) {
    extern __shared__ float sm[];
    uint32_t* s_w    = (uint32_t*)sm;             // 3 x 2048
    uint32_t* s_colh = s_w + 3 * 2048;            // 2 x 2112

    const int tid = threadIdx.x;
    const int wid = tid >> 5, lane = tid & 31;
    const int warp_m = wid >> 2, warp_n = wid & 3;
    const int lm = lane >> 2, lk = lane & 3;
    const int b = blockIdx.y;
    const int tile_x = (blockIdx.x % 3) * 32;
    const int tile_y = (blockIdx.x / 3) * 4;

    const int px_own = tid & 127;
    const int h      = tid >> 7;
    const int gy_own = tile_y + (px_own >> 5);
    const int gx_own = tile_x + (px_own & 31);

    float cacc[4][4][4];
#pragma unroll
    for (int mt = 0; mt < 4; mt++)
#pragma unroll
        for (int nt = 0; nt < 4; nt++)
#pragma unroll
            for (int i = 0; i < 4; i++) cacc[mt][nt][i] = 0.f;

    int pxidx[4], rowb[4];
#pragma unroll
    for (int nt = 0; nt < 4; nt++)
        pxidx[nt] = warp_n * 32 + nt * 8 + lm;
#pragma unroll
    for (int mt = 0; mt < 4; mt++)
        rowb[mt] = warp_m * 64 + mt * 16 + lm;

    const float* cob = g_co + (size_t)b * OC2 * HWSZ;

    auto phaseA_reg = [&](int idx, int4& iv, float4& wv) {
        int g = idx / 9, k = idx - g * 9;
        int c_y = g * 18 + 2 * k;
        const float* basep = cob + gy_own * HW + gx_own;
        float offy = basep[(size_t)c_y * HWSZ];
        float offx = basep[(size_t)(c_y + 1) * HWSZ];
        float mraw = basep[(size_t)(72 + g * 9 + k) * HWSZ];
        float m  = 1.f / (1.f + __expf(-mraw));
        float ys = (float)gy_own + (float)(k / 3 - 1) + offy;
        float xs = (float)gx_own + (float)(k % 3 - 1) + offx;
        float y0f = floorf(ys), x0f = floorf(xs);
        float fy = ys - y0f, fx = xs - x0f;
        int y0 = (int)y0f, x0 = (int)x0f;
        int idxs[4]; float wgts[4];
#pragma unroll
        for (int cnr = 0; cnr < 4; cnr++) {
            int dy = cnr >> 1, dx = cnr & 1;
            int yi = y0 + dy, xi = x0 + dx;
            bool valid = (yi >= 0) && (yi < HW) && (xi >= 0) && (xi < HW);
            float wy = dy ? fy : (1.f - fy);
            float wx = dx ? fx : (1.f - fx);
            int yc = min(max(yi, 0), HW - 1);
            int xc = min(max(xi, 0), HW - 1);
            idxs[cnr] = yc * HW + xc;
            wgts[cnr] = valid ? (wy * wx * m) : 0.f;
        }
        iv = make_int4(idxs[0], idxs[1], idxs[2], idxs[3]);
        wv = make_float4(wgts[0], wgts[1], wgts[2], wgts[3]);
    };

    auto corner_ld = [&](const uint32_t* xgp, int piv, float v[16]) {
#pragma unroll
        for (int cp = 0; cp < 8; cp++) {
            uint32_t u = __ldg(xgp + (size_t)cp * HWSZ + piv);
            __half2 hh = *reinterpret_cast<__half2*>(&u);
            float2 f = __half22float2(hh);
            v[2 * cp] = f.x; v[2 * cp + 1] = f.y;
        }
    };

    auto store_col = [&](int it1, const float acc[16]) {
        uint2* col2 = (uint2*)(s_colh + (it1 & 1) * COLB32);
#pragma unroll
        for (int lkp = 0; lkp < 4; lkp++) {
            col2[(4 * h + lkp) * COL_S + px_own] =
                make_uint2(pack_h2(acc[2 * lkp], acc[2 * lkp + 1]),
                           pack_h2(acc[2 * lkp + 8], acc[2 * lkp + 9]));
        }
    };

    auto do_mma_s = [&](int it, int wslot, int s) {
        const uint2* swc4 = (const uint2*)(s_w + wslot * 2048);
        const uint2* col2 = (const uint2*)(s_colh + (it & 1) * COLB32);
        uint32_t A[4][4], B4[4][2];
#pragma unroll
        for (int mt = 0; mt < 4; mt++) {
            int r0 = rowb[mt];
            uint2 u = swc4[r0 * 8 + ((s * 4 + lk + r0) & 7)];
            uint2 v = swc4[(r0 + 8) * 8 + ((s * 4 + lk + r0) & 7)];
            A[mt][0] = u.x; A[mt][1] = v.x; A[mt][2] = u.y; A[mt][3] = v.y;
        }
#pragma unroll
        for (int nt = 0; nt < 4; nt++) {
            uint2 f = col2[(s * 4 + lk) * COL_S + pxidx[nt]];
            B4[nt][0] = f.x; B4[nt][1] = f.y;
        }
#pragma unroll
        for (int mt = 0; mt < 4; mt++)
#pragma unroll
            for (int nt = 0; nt < 4; nt++)
                mma16(cacc[mt][nt], A[mt], B4[nt]);
    };

    // ---- prologue: tap 0 gather ----
    prefetch_w_cp(s_w + 0 * 2048, g_wdh, tid);
    prefetch_w_cp(s_w + 1 * 2048, g_wdh + 2048, tid);
    {
        int4 iv; float4 wv;
        phaseA_reg(0, iv, wv);
        const uint32_t* xgp = g_xh + ((size_t)(b * NDG + 0) * 16 + 8 * h) * HWSZ;
        float acc[16], cv[16];
        corner_ld(xgp, iv.x, cv);
#pragma unroll
        for (int j = 0; j < 16; j++) acc[j] = wv.x * cv[j];
        corner_ld(xgp, iv.y, cv);
#pragma unroll
        for (int j = 0; j < 16; j++) acc[j] = fmaf(wv.y, cv[j], acc[j]);
        corner_ld(xgp, iv.z, cv);
#pragma unroll
        for (int j = 0; j < 16; j++) acc[j] = fmaf(wv.z, cv[j], acc[j]);
        corner_ld(xgp, iv.w, cv);
#pragma unroll
        for (int j = 0; j < 16; j++) acc[j] = fmaf(wv.w, cv[j], acc[j]);
        store_col(0, acc);
    }

    // ---- main pipeline ----
    int wslot = 0, pslot = 2;
    for (int it = 0; it < 36; it++) {
        int4 ivn; float4 wvn;
        if (it < 35) phaseA_reg(it + 1, ivn, wvn);
        CP_WAIT_ALL();
        __syncthreads();
        if (it < 34) prefetch_w_cp(s_w + pslot * 2048, g_wdh + (size_t)(it + 2) * 2048, tid);
        if (it < 35) {
            const int gn = (it + 1) / 9;
            const uint32_t* xgp = g_xh + ((size_t)(b * NDG + gn) * 16 + 8 * h) * HWSZ;
            float acc[16], cv[16];
            corner_ld(xgp, ivn.x, cv);
            do_mma_s(it, wslot, 0);
#pragma unroll
            for (int j = 0; j < 16; j++) acc[j] = wvn.x * cv[j];
            corner_ld(xgp, ivn.y, cv);
#pragma unroll
            for (int j = 0; j < 16; j++) acc[j] = fmaf(wvn.y, cv[j], acc[j]);
            corner_ld(xgp, ivn.z, cv);
            do_mma_s(it, wslot, 1);
#pragma unroll
            for (int j = 0; j < 16; j++) acc[j] = fmaf(wvn.z, cv[j], acc[j]);
            corner_ld(xgp, ivn.w, cv);
#pragma unroll
            for (int j = 0; j < 16; j++) acc[j] = fmaf(wvn.w, cv[j], acc[j]);
            store_col(it + 1, acc);
        } else {
            do_mma_s(it, wslot, 0);
            do_mma_s(it, wslot, 1);
        }
        wslot = (wslot == 2) ? 0 : wslot + 1;
        pslot = (pslot == 2) ? 0 : pslot + 1;
    }

    // epilogue
#pragma unroll
    for (int mt = 0; mt < 4; mt++) {
        int oc0 = warp_m * 64 + mt * 16 + lm;
        int oc1 = oc0 + 8;
        float bz0 = bias[oc0], bz1 = bias[oc1];
#pragma unroll
        for (int nt = 0; nt < 4; nt++) {
            int px0 = warp_n * 32 + nt * 8 + lk * 2;
            int gy = tile_y + (px0 >> 5), gx = tile_x + (px0 & 31);
            *reinterpret_cast<float2*>(&y[((size_t)(b * OC1 + oc0)) * HWSZ + gy * HW + gx]) =
                make_float2(cacc[mt][nt][0] + bz0, cacc[mt][nt][1] + bz0);
            *reinterpret_cast<float2*>(&y[((size_t)(b * OC1 + oc1)) * HWSZ + gy * HW + gx]) =
                make_float2(cacc[mt][nt][2] + bz1, cacc[mt][nt][3] + bz1);
        }
    }
}

// ---------------- launch ----------------
extern "C" void kernel_launch(void* const* d_in, const int* in_sizes, int n_in,
                              void* d_out, int out_size) {
    (void)in_sizes; (void)n_in; (void)out_size;
    const float* x_vq  = (const float*)d_in[0];
    const float* w_off = (const float*)d_in[1];
    const float* b_off = (const float*)d_in[2];
    const float* w_co  = (const float*)d_in[3];
    const float* b_co  = (const float*)d_in[4];
    const float* w_dcn = (const float*)d_in[5];
    const float* b_dcn = (const float*)d_in[6];
    float* out = (float*)d_out;

    cudaFuncSetAttribute(conv_mma_kernel<OC1, 0>, cudaFuncAttributeMaxDynamicSharedMemorySize, CONV_SMEM);
    cudaFuncSetAttribute(conv_mma_kernel<OC2, 1>, cudaFuncAttributeMaxDynamicSharedMemorySize, CONV_SMEM);
    cudaFuncSetAttribute(dcn_mma_kernel, cudaFuncAttributeMaxDynamicSharedMemorySize, DCN_SMEM);

    prep_wh_kernel<<<864, 256>>>(w_off, w_co, w_dcn);
    prep_xh_kernel<<<(BATCH * 64 * HWSZ + 255) / 256, 256>>>(x_vq);

    dim3 cgrid(72, BATCH);   // 3x24 tiles of 32x4 px, 128 oc per CTA
    conv_mma_kernel<OC1, 0><<<cgrid, 256, CONV_SMEM>>>(b_off);
    conv_mma_kernel<OC2, 1><<<cgrid, 256, CONV_SMEM>>>(b_co);

    dim3 dgrid(72, BATCH);
    dcn_mma_kernel<<<dgrid, 256, DCN_SMEM>>>(b_dcn, out);
}